// round 2
// baseline (speedup 1.0000x reference)
#include <cuda_runtime.h>
#include <math.h>

// ---------------- problem constants ----------------
constexpr int Bsz = 32, T = 1024, D = 256, NH = 2, DK = 128, DH = 1024, L = 4;
constexpr int M_ALL = Bsz * T;          // 32768 rows
constexpr int TPAD  = T + 8;            // conv1 halo (4 each side)
constexpr float EPS = 1e-5f;

// ---------------- device scratch (static, no allocations) ----------------
__device__ float g_h     [ (long)M_ALL * D ];          // ln1 output
__device__ float g_qkv   [ (long)M_ALL * 3 * D ];      // qkv projections
__device__ float g_scores[ (long)Bsz * NH * T * T ];   // attention scores (268MB)
__device__ float g_attno [ (long)M_ALL * D ];          // attention output (heads merged)
__device__ float g_hpad  [ (long)Bsz * TPAD * D ];     // ln2 output, 4-row zero halo per batch
__device__ float g_hid   [ (long)M_ALL * DH ];         // conv1 output (relu'd)
__device__ float g_wt1   [ (long)L * DH * D * 9 ];     // conv1 weights repacked [l][o][kk*D+i]
__device__ float g_nonpad[ M_ALL ];                    // (seq != 0) as float

// ---------------- reductions ----------------
__device__ __forceinline__ float blockReduceSum(float v) {
    __shared__ float sh[8];
    int lane = threadIdx.x & 31, w = threadIdx.x >> 5;
    #pragma unroll
    for (int o = 16; o; o >>= 1) v += __shfl_xor_sync(0xffffffffu, v, o);
    if (!lane) sh[w] = v;
    __syncthreads();
    if (w == 0) {
        v = (lane < 8) ? sh[lane] : 0.f;
        #pragma unroll
        for (int o = 4; o; o >>= 1) v += __shfl_xor_sync(0xffffffffu, v, o);
        if (!lane) sh[0] = v;
    }
    __syncthreads();
    float r = sh[0];
    __syncthreads();
    return r;
}

__device__ __forceinline__ float blockReduceMax(float v) {
    __shared__ float sh[8];
    int lane = threadIdx.x & 31, w = threadIdx.x >> 5;
    #pragma unroll
    for (int o = 16; o; o >>= 1) v = fmaxf(v, __shfl_xor_sync(0xffffffffu, v, o));
    if (!lane) sh[w] = v;
    __syncthreads();
    if (w == 0) {
        v = (lane < 8) ? sh[lane] : -3.0e38f;
        #pragma unroll
        for (int o = 4; o; o >>= 1) v = fmaxf(v, __shfl_xor_sync(0xffffffffu, v, o));
        if (!lane) sh[0] = v;
    }
    __syncthreads();
    float r = sh[0];
    __syncthreads();
    return r;
}

// ---------------- small kernels ----------------
__global__ void embed_k(const int* __restrict__ seq, const int* __restrict__ pos,
                        const float* __restrict__ we, const float* __restrict__ pe,
                        float* __restrict__ x) {
    int r = blockIdx.x, d = threadIdx.x;
    int s = seq[r], p = pos[r];
    x[(long)r * D + d] = we[(long)s * D + d] + pe[(long)p * D + d];
    if (d == 0) g_nonpad[r] = (s != 0) ? 1.f : 0.f;
}

// padmode 0: out row r at out+r*D ; padmode 1: out row at hpad interior (+4 rows)
__global__ void ln_k(const float* __restrict__ x, const float* __restrict__ g,
                     const float* __restrict__ bb, float* __restrict__ out, int padmode) {
    int r = blockIdx.x, d = threadIdx.x;
    float v = x[(long)r * D + d];
    float mean = blockReduceSum(v) * (1.f / D);
    float c = v - mean;
    float var = blockReduceSum(c * c) * (1.f / D);
    float y = c * rsqrtf(var + EPS) * g[d] + bb[d];
    long o;
    if (padmode) {
        int b = r / T, t = r % T;
        o = ((long)b * TPAD + t + 4) * D + d;
    } else {
        o = (long)r * D + d;
    }
    out[o] = y;
}

__global__ void zero_halo_k() {
    int idx = blockIdx.x * blockDim.x + threadIdx.x;   // Bsz*8*D = 65536
    int b = idx / (8 * D);
    int rr = (idx / D) % 8;
    int d = idx % D;
    int t = (rr < 4) ? rr : (T + 4 + rr - 4);
    g_hpad[((long)b * TPAD + t) * D + d] = 0.f;
}

__global__ void repack_w1_k(const float* __restrict__ w) {
    long i = (long)blockIdx.x * blockDim.x + threadIdx.x;
    const long total = (long)L * DH * D * 9;
    if (i >= total) return;
    long base = i / (D * 9);        // l*DH + o
    int p = (int)(i % (D * 9));     // kk*D + ii
    int kk = p / D, ii = p % D;
    g_wt1[i] = w[base * (D * 9) + (long)ii * 9 + kk];
}

__global__ void softmax_k(float* __restrict__ sc, const int* __restrict__ seq) {
    long row = blockIdx.x;                 // B*NH*T rows
    int b = (int)(row / ((long)NH * T));
    float* p = sc + row * T;
    const int* sq = seq + (long)b * T;
    const float scale = 0.08838834764831845f;  // 1/sqrt(128)
    int tid = threadIdx.x;
    float vals[4];
    float mx = -3.0e38f;
    #pragma unroll
    for (int q = 0; q < 4; q++) {
        int k = tid + q * 256;
        float v = (sq[k] == 0) ? -3.0e38f : p[k] * scale;
        vals[q] = v;
        mx = fmaxf(mx, v);
    }
    float M = blockReduceMax(mx);
    float s = 0.f;
    #pragma unroll
    for (int q = 0; q < 4; q++) {
        float e = __expf(vals[q] - M);
        vals[q] = e;
        s += e;
    }
    float S = blockReduceSum(s);
    float inv = 1.f / S;
    #pragma unroll
    for (int q = 0; q < 4; q++) p[tid + q * 256] = vals[q] * inv;
}

__global__ void copy_np_k(float* __restrict__ out) {
    int i = blockIdx.x * blockDim.x + threadIdx.x;
    if (i < M_ALL) out[i] = g_nonpad[i];
}

// ---------------- generic batched SGEMM (double-buffered smem) ----------------
// C[m,n] = sum_k A[m,k] * (BT ? B[n,k] : B[k,n])
// epilogue: +bias[n], relu, +resid (C-shaped), *mask[m]
// batch z: b = z/H, h = z%H with per-(b,h) pointer strides.
// Requirements: M,N multiples of 128; K multiple of 8 and >= 16; ld* multiples of 4.
template <bool BT>
__global__ __launch_bounds__(256)
void sgemm_k(const float* __restrict__ A, int lda, long aSb, long aSh,
             const float* __restrict__ Bm, int ldb, long bSb, long bSh,
             float* __restrict__ C, int ldc, long cSb, long cSh,
             int K, int H,
             const float* __restrict__ bias,
             const float* __restrict__ resid,
             const float* __restrict__ mask,
             int relu) {
    int z = blockIdx.z;
    int zb = z / H, zh = z % H;
    A  += (long)zb * aSb + (long)zh * aSh;
    Bm += (long)zb * bSb + (long)zh * bSh;
    C  += (long)zb * cSb + (long)zh * cSh;
    if (resid) resid += (long)zb * cSb + (long)zh * cSh;

    __shared__ float As[2][8][128];
    __shared__ float Bs[2][8][128];

    int tid = threadIdx.x;
    int m0 = blockIdx.x * 128, n0 = blockIdx.y * 128;

    int lm  = tid >> 1;            // 0..127
    int lk  = (tid & 1) * 4;       // 0 or 4
    int lkb = tid >> 5;            // 0..7   (NN B loads)
    int lnb = (tid & 31) * 4;      // 0..124

    int tx = tid & 15, ty = tid >> 4;
    float acc[8][8];
    #pragma unroll
    for (int i = 0; i < 8; i++)
        #pragma unroll
        for (int j = 0; j < 8; j++) acc[i][j] = 0.f;

    // prologue: load first K-tile into buffer 0
    {
        float4 av = *(const float4*)(A + (long)(m0 + lm) * lda + lk);
        As[0][lk + 0][lm] = av.x; As[0][lk + 1][lm] = av.y;
        As[0][lk + 2][lm] = av.z; As[0][lk + 3][lm] = av.w;
        if (BT) {
            float4 bv = *(const float4*)(Bm + (long)(n0 + lm) * ldb + lk);
            Bs[0][lk + 0][lm] = bv.x; Bs[0][lk + 1][lm] = bv.y;
            Bs[0][lk + 2][lm] = bv.z; Bs[0][lk + 3][lm] = bv.w;
        } else {
            float4 bv = *(const float4*)(Bm + (long)lkb * ldb + n0 + lnb);
            *(float4*)&Bs[0][lkb][lnb] = bv;
        }
    }
    __syncthreads();

    int buf = 0;
    for (int k0 = 0; k0 < K; k0 += 8) {
        // issue next tile's global loads early (into registers)
        float4 av, bv;
        bool more = (k0 + 8) < K;
        if (more) {
            av = *(const float4*)(A + (long)(m0 + lm) * lda + k0 + 8 + lk);
            if (BT) bv = *(const float4*)(Bm + (long)(n0 + lm) * ldb + k0 + 8 + lk);
            else    bv = *(const float4*)(Bm + (long)(k0 + 8 + lkb) * ldb + n0 + lnb);
        }
        // compute on current buffer
        #pragma unroll
        for (int kk = 0; kk < 8; kk++) {
            float a[8], b[8];
            *(float4*)(a)     = *(const float4*)&As[buf][kk][ty * 8];
            *(float4*)(a + 4) = *(const float4*)&As[buf][kk][ty * 8 + 4];
            *(float4*)(b)     = *(const float4*)&Bs[buf][kk][tx * 8];
            *(float4*)(b + 4) = *(const float4*)&Bs[buf][kk][tx * 8 + 4];
            #pragma unroll
            for (int i = 0; i < 8; i++)
                #pragma unroll
                for (int j = 0; j < 8; j++)
                    acc[i][j] = fmaf(a[i], b[j], acc[i][j]);
        }
        // store next tile into the other buffer
        if (more) {
            int nb = buf ^ 1;
            As[nb][lk + 0][lm] = av.x; As[nb][lk + 1][lm] = av.y;
            As[nb][lk + 2][lm] = av.z; As[nb][lk + 3][lm] = av.w;
            if (BT) {
                Bs[nb][lk + 0][lm] = bv.x; Bs[nb][lk + 1][lm] = bv.y;
                Bs[nb][lk + 2][lm] = bv.z; Bs[nb][lk + 3][lm] = bv.w;
            } else {
                *(float4*)&Bs[nb][lkb][lnb] = bv;
            }
            __syncthreads();
            buf = nb;
        }
    }

    #pragma unroll
    for (int i = 0; i < 8; i++) {
        int m = m0 + ty * 8 + i;
        float mk = mask ? mask[m] : 1.f;
        #pragma unroll
        for (int j = 0; j < 8; j++) {
            int n = n0 + tx * 8 + j;
            float v = acc[i][j];
            if (bias) v += bias[n];
            if (relu) v = fmaxf(v, 0.f);
            if (resid) v += resid[(long)m * ldc + n];
            v *= mk;
            C[(long)m * ldc + n] = v;
        }
    }
}

// ---------------- host orchestration ----------------
extern "C" void kernel_launch(void* const* d_in, const int* in_sizes, int n_in,
                              void* d_out, int out_size) {
    const int*   src_seq  = (const int*)  d_in[0];
    const int*   src_pos  = (const int*)  d_in[1];
    const float* word_emb = (const float*)d_in[2];
    const float* pos_emb  = (const float*)d_in[3];
    const float* qkv_w    = (const float*)d_in[4];
    const float* qkv_b    = (const float*)d_in[5];
    const float* fc_w     = (const float*)d_in[6];
    const float* fc_b     = (const float*)d_in[7];
    const float* ln1_g    = (const float*)d_in[8];
    const float* ln1_b    = (const float*)d_in[9];
    const float* conv1_w  = (const float*)d_in[10];
    const float* conv1_b  = (const float*)d_in[11];
    const float* conv2_w  = (const float*)d_in[12];
    const float* conv2_b  = (const float*)d_in[13];
    const float* ln2_g    = (const float*)d_in[14];
    const float* ln2_b    = (const float*)d_in[15];

    float* x = (float*)d_out;   // residual stream lives in d_out

    float *p_h, *p_qkv, *p_sc, *p_ao, *p_hpad, *p_hid, *p_wt1, *p_np;
    cudaGetSymbolAddress((void**)&p_h,    g_h);
    cudaGetSymbolAddress((void**)&p_qkv,  g_qkv);
    cudaGetSymbolAddress((void**)&p_sc,   g_scores);
    cudaGetSymbolAddress((void**)&p_ao,   g_attno);
    cudaGetSymbolAddress((void**)&p_hpad, g_hpad);
    cudaGetSymbolAddress((void**)&p_hid,  g_hid);
    cudaGetSymbolAddress((void**)&p_wt1,  g_wt1);
    cudaGetSymbolAddress((void**)&p_np,   g_nonpad);

    // one-time-per-call prep
    zero_halo_k<<<(Bsz * 8 * D) / 256, 256>>>();
    {
        long total = (long)L * DH * D * 9;
        repack_w1_k<<<(int)((total + 255) / 256), 256>>>(conv1_w);
    }
    embed_k<<<M_ALL, D>>>(src_seq, src_pos, word_emb, pos_emb, x);

    const long S_qkvB = (long)T * 3 * D;   // per-batch stride in qkv
    for (int l = 0; l < L; l++) {
        // ---- attention sublayer ----
        ln_k<<<M_ALL, D>>>(x, ln1_g + l * D, ln1_b + l * D, p_h, 0);

        // qkv: [32768,256] x [768,256]^T -> [32768,768]
        sgemm_k<true><<<dim3(M_ALL / 128, (3 * D) / 128, 1), 256>>>(
            p_h, D, 0, 0,
            qkv_w + (long)l * 3 * D * D, D, 0, 0,
            p_qkv, 3 * D, 0, 0,
            D, 1, qkv_b + l * 3 * D, nullptr, nullptr, 0);

        // scores: per (b,h): Q[1024,128] x K^T -> [1024,1024]
        sgemm_k<true><<<dim3(T / 128, T / 128, Bsz * NH), 256>>>(
            p_qkv,           3 * D, S_qkvB, DK,        // Q
            p_qkv + D,       3 * D, S_qkvB, DK,        // K
            p_sc, T, (long)NH * T * T, (long)T * T,
            DK, NH, nullptr, nullptr, nullptr, 0);

        softmax_k<<<Bsz * NH * T, 256>>>(p_sc, src_seq);

        // attn out: P[1024,1024] x V[1024,128] -> [1024,128]  (NN)
        sgemm_k<false><<<dim3(T / 128, DK / 128, Bsz * NH), 256>>>(
            p_sc, T, (long)NH * T * T, (long)T * T,
            p_qkv + 2 * D, 3 * D, S_qkvB, DK,          // V
            p_ao, D, (long)T * D, DK,
            T, NH, nullptr, nullptr, nullptr, 0);

        // fc + residual + pad-mask -> x
        sgemm_k<true><<<dim3(M_ALL / 128, D / 128, 1), 256>>>(
            p_ao, D, 0, 0,
            fc_w + (long)l * D * D, D, 0, 0,
            x, D, 0, 0,
            D, 1, fc_b + l * D, x, p_np, 0);

        // ---- conv FFN sublayer ----
        ln_k<<<M_ALL, D>>>(x, ln2_g + l * D, ln2_b + l * D, p_hpad, 1);

        // conv1 as NT GEMM: per batch A=hpad[b] (lda=D, overlapping rows), K=2304
        sgemm_k<true><<<dim3(T / 128, DH / 128, Bsz), 256>>>(
            p_hpad, D, (long)TPAD * D, 0,
            p_wt1 + (long)l * DH * D * 9, D * 9, 0, 0,
            p_hid, DH, (long)T * DH, 0,
            D * 9, 1, conv1_b + l * DH, nullptr, nullptr, 1 /*relu*/);

        // conv2 (k=1) + residual + pad-mask -> x
        sgemm_k<true><<<dim3(M_ALL / 128, D / 128, 1), 256>>>(
            p_hid, DH, 0, 0,
            conv2_w + (long)l * D * DH, DH, 0, 0,
            x, D, 0, 0,
            DH, 1, conv2_b + l * D, x, p_np, 0);
    }

    // second output of the reference tuple: non_pad [B,T,1]
    if (out_size >= M_ALL * D + M_ALL) {
        copy_np_k<<<M_ALL / 256, 256>>>((float*)d_out + (long)M_ALL * D);
    }
}